// round 11
// baseline (speedup 1.0000x reference)
#include <cuda_runtime.h>
#include <cuda_fp16.h>
#include <math.h>

// Shapes (fixed per reference): B=8, C=512, Ck=Cv=256, Co=512, H=W=64, N=4096
#define NB 8
#define NC 512
#define NCK 256
#define NCO 512
#define NN 4096

// Softmax shift: logits = (feat_i . feat_j)/16 in [0, ~13.5]; exp(l-8) fp16-safe.
#define SM_SHIFT 8.0f

// Scratch (allocation-free: __device__ globals)
__device__ float  g_qk[(size_t)NB * NCK * NN];          // 33.5 MB: pre-BN qk
__device__ __half g_vh[(size_t)NB * NCK * NN];          // 16.8 MB: value fp16 [cv][n]
__device__ __half g_fhT[(size_t)NB * NN * NCK];         // 16.8 MB: feat fp16 [n][k]
__device__ __half g_ctxh[(size_t)NB * NN * NCK];        // 16.8 MB: ctx fp16 [n][cv]
__device__ float  g_bnp1[NCK * 256];                    // BN partial sums
__device__ float  g_bnp2[NCK * 256];                    // BN partial sq-sums
__device__ float  g_mean[NCK];
__device__ float  g_rstd[NCK];

__device__ __forceinline__ void mma_f16(
    float& c0, float& c1, float& c2, float& c3,
    unsigned a0, unsigned a1, unsigned a2, unsigned a3,
    unsigned b0, unsigned b1)
{
    asm volatile(
        "mma.sync.aligned.m16n8k16.row.col.f32.f16.f16.f32 "
        "{%0,%1,%2,%3}, {%4,%5,%6,%7}, {%8,%9}, {%0,%1,%2,%3};"
        : "+f"(c0), "+f"(c1), "+f"(c2), "+f"(c3)
        : "r"(a0), "r"(a1), "r"(a2), "r"(a3), "r"(b0), "r"(b1));
}

// ---------------------------------------------------------------------------
// Generic strided fp16-input tensor-core GEMM (convs).
// A fp32 (converted at SMEM store). B fp32 if !BH, fp16 if BH.
// MODE 0: plain.  MODE 3: + fp16 copy of C.  MODE 4: + BN partials.
// ---------------------------------------------------------------------------
template<int MODE, bool BH>
__global__ __launch_bounds__(256, 2) void gemm_f16(
    const float* __restrict__ A, const void* __restrict__ Bv,
    float* __restrict__ C, const float* __restrict__ bias,
    int K,
    long sa_m, long sa_k, long sb_k, long sb_n, long sc_m,
    long bA, long bB, long bC, float alpha,
    __half* __restrict__ Ch)
{
    __shared__ __half As[128][40];
    __shared__ __half Bs[128][40];
    __shared__ float red1[128][4];
    __shared__ float red2[128][4];

    const int bz = blockIdx.z;
    A += (size_t)bz * bA;
    const float*  Bf  = (const float*)Bv + (BH ? 0 : (size_t)bz * bB);
    const __half* Bhp = (const __half*)Bv + (BH ? (size_t)bz * bB : 0);
    C += (size_t)bz * bC;
    if (MODE == 3) Ch += (size_t)bz * bC;

    const int m0 = blockIdx.y * 128;
    const int n0 = blockIdx.x * 128;
    const int tid  = threadIdx.x;
    const int warp = tid >> 5;
    const int lane = tid & 31;
    const int wm = (warp & 1) * 64;
    const int wn = (warp >> 1) * 32;
    const int gid = lane >> 2;
    const int tig = lane & 3;

    float acc[4][4][4];
#pragma unroll
    for (int i = 0; i < 4; i++)
#pragma unroll
        for (int j = 0; j < 4; j++)
#pragma unroll
            for (int c = 0; c < 4; c++) acc[i][j][c] = 0.f;

    for (int k0 = 0; k0 < K; k0 += 32) {
        if (sa_k == 1) {
            const int m = tid >> 3, kq = (tid & 7) * 4;
#pragma unroll
            for (int i = 0; i < 4; i++) {
                float4 v = *(const float4*)&A[(size_t)(m0 + m + 32 * i) * sa_m + (size_t)(k0 + kq)];
                __half2 h0 = __floats2half2_rn(v.x, v.y);
                __half2 h1 = __floats2half2_rn(v.z, v.w);
                *(uint2*)&As[m + 32 * i][kq] = make_uint2(*(unsigned*)&h0, *(unsigned*)&h1);
            }
        } else {
            const int m = tid & 127, kb = (tid >> 7) * 16;
            const float* Ap = A + (size_t)(m0 + m) + (size_t)(k0 + kb) * sa_k;
#pragma unroll
            for (int q = 0; q < 4; q++) {
                __half2 h0 = __floats2half2_rn(Ap[(size_t)(q * 4 + 0) * sa_k],
                                               Ap[(size_t)(q * 4 + 1) * sa_k]);
                __half2 h1 = __floats2half2_rn(Ap[(size_t)(q * 4 + 2) * sa_k],
                                               Ap[(size_t)(q * 4 + 3) * sa_k]);
                *(uint2*)&As[m][kb + q * 4] = make_uint2(*(unsigned*)&h0, *(unsigned*)&h1);
            }
        }
        if (sb_n == 1) {
            const int n = tid & 127, kb = (tid >> 7) * 16;
            if (!BH) {
                const float* Bp = Bf + (size_t)(n0 + n) + (size_t)(k0 + kb) * sb_k;
#pragma unroll
                for (int q = 0; q < 4; q++) {
                    __half2 h0 = __floats2half2_rn(Bp[(size_t)(q * 4 + 0) * sb_k],
                                                   Bp[(size_t)(q * 4 + 1) * sb_k]);
                    __half2 h1 = __floats2half2_rn(Bp[(size_t)(q * 4 + 2) * sb_k],
                                                   Bp[(size_t)(q * 4 + 3) * sb_k]);
                    *(uint2*)&Bs[n][kb + q * 4] = make_uint2(*(unsigned*)&h0, *(unsigned*)&h1);
                }
            } else {
                const __half* Bp = Bhp + (size_t)(n0 + n) + (size_t)(k0 + kb) * sb_k;
#pragma unroll
                for (int q = 0; q < 16; q++)
                    Bs[n][kb + q] = Bp[(size_t)q * sb_k];
            }
        } else {  // sb_k == 1
            const int n = tid >> 3, kq = (tid & 7) * 4;
            if (!BH) {
#pragma unroll
                for (int i = 0; i < 4; i++) {
                    float4 v = *(const float4*)&Bf[(size_t)(n0 + n + 32 * i) * sb_n + (size_t)(k0 + kq)];
                    __half2 h0 = __floats2half2_rn(v.x, v.y);
                    __half2 h1 = __floats2half2_rn(v.z, v.w);
                    *(uint2*)&Bs[n + 32 * i][kq] = make_uint2(*(unsigned*)&h0, *(unsigned*)&h1);
                }
            } else {
#pragma unroll
                for (int i = 0; i < 4; i++) {
                    uint2 v = *(const uint2*)&Bhp[(size_t)(n0 + n + 32 * i) * sb_n + (size_t)(k0 + kq)];
                    *(uint2*)&Bs[n + 32 * i][kq] = v;
                }
            }
        }
        __syncthreads();

#pragma unroll
        for (int sl = 0; sl < 2; sl++) {
            const int kk = sl * 16;
            unsigned a[4][4];
#pragma unroll
            for (int mt = 0; mt < 4; mt++) {
                const int mr = wm + mt * 16;
                a[mt][0] = *(const unsigned*)&As[mr + gid][kk + 2 * tig];
                a[mt][1] = *(const unsigned*)&As[mr + gid + 8][kk + 2 * tig];
                a[mt][2] = *(const unsigned*)&As[mr + gid][kk + 2 * tig + 8];
                a[mt][3] = *(const unsigned*)&As[mr + gid + 8][kk + 2 * tig + 8];
            }
            unsigned b[4][2];
#pragma unroll
            for (int nt = 0; nt < 4; nt++) {
                const int nr = wn + nt * 8 + gid;
                b[nt][0] = *(const unsigned*)&Bs[nr][kk + 2 * tig];
                b[nt][1] = *(const unsigned*)&Bs[nr][kk + 2 * tig + 8];
            }
#pragma unroll
            for (int mt = 0; mt < 4; mt++)
#pragma unroll
                for (int nt = 0; nt < 4; nt++)
                    mma_f16(acc[mt][nt][0], acc[mt][nt][1], acc[mt][nt][2], acc[mt][nt][3],
                            a[mt][0], a[mt][1], a[mt][2], a[mt][3],
                            b[nt][0], b[nt][1]);
        }
        __syncthreads();
    }

#pragma unroll
    for (int mt = 0; mt < 4; mt++) {
        const int r0 = m0 + wm + mt * 16 + gid;
        const float bb0 = bias ? bias[r0] : 0.f;
        const float bb1 = bias ? bias[r0 + 8] : 0.f;
        float s1a = 0.f, s2a = 0.f, s1b = 0.f, s2b = 0.f;
#pragma unroll
        for (int nt = 0; nt < 4; nt++) {
            const int col = n0 + wn + nt * 8 + 2 * tig;
            float2 v0 = make_float2(acc[mt][nt][0] * alpha + bb0, acc[mt][nt][1] * alpha + bb0);
            float2 v1 = make_float2(acc[mt][nt][2] * alpha + bb1, acc[mt][nt][3] * alpha + bb1);
            *(float2*)&C[(size_t)r0 * sc_m + col] = v0;
            *(float2*)&C[(size_t)(r0 + 8) * sc_m + col] = v1;
            if (MODE == 3) {
                *(__half2*)&Ch[(size_t)r0 * sc_m + col] = __floats2half2_rn(v0.x, v0.y);
                *(__half2*)&Ch[(size_t)(r0 + 8) * sc_m + col] = __floats2half2_rn(v1.x, v1.y);
            }
            if (MODE == 4) {
                s1a += v0.x + v0.y;
                s2a = fmaf(v0.x, v0.x, fmaf(v0.y, v0.y, s2a));
                s1b += v1.x + v1.y;
                s2b = fmaf(v1.x, v1.x, fmaf(v1.y, v1.y, s2b));
            }
        }
        if (MODE == 4) {
            s1a += __shfl_xor_sync(0xffffffffu, s1a, 1);
            s1a += __shfl_xor_sync(0xffffffffu, s1a, 2);
            s2a += __shfl_xor_sync(0xffffffffu, s2a, 1);
            s2a += __shfl_xor_sync(0xffffffffu, s2a, 2);
            s1b += __shfl_xor_sync(0xffffffffu, s1b, 1);
            s1b += __shfl_xor_sync(0xffffffffu, s1b, 2);
            s2b += __shfl_xor_sync(0xffffffffu, s2b, 1);
            s2b += __shfl_xor_sync(0xffffffffu, s2b, 2);
            if (tig == 0) {
                const int lr = wm + mt * 16 + gid;
                const int nw = warp >> 1;
                red1[lr][nw] = s1a;  red2[lr][nw] = s2a;
                red1[lr + 8][nw] = s1b;  red2[lr + 8][nw] = s2b;
            }
        }
    }
    if (MODE == 4) {
        __syncthreads();
        if (tid < 128) {
            float S1 = red1[tid][0] + red1[tid][1] + red1[tid][2] + red1[tid][3];
            float S2 = red2[tid][0] + red2[tid][1] + red2[tid][2] + red2[tid][3];
            const int slot = bz * 32 + blockIdx.x;
            g_bnp1[(m0 + tid) * 256 + slot] = S1;
            g_bnp2[(m0 + tid) * 256 + slot] = S2;
        }
    }
}

// ---------------------------------------------------------------------------
// Fused flash attention: for a 128-query tile, loop 64-key tiles:
//   S = Q K^T (fp16 MMA, k=256), P = exp(S/16 - 8) -> SMEM (fp16),
//   O += P V^T (fp16 MMA, k=64), rowsum accumulated in fp32 registers.
// Epilogue: ctx = O / rowsum -> fp16 [n][cv]. P never hits gmem.
// Q: g_fhT [n][k]. V: g_vh [cv][n]. One CTA per (query tile, batch).
// ---------------------------------------------------------------------------
__global__ __launch_bounds__(256, 1) void flash_attn(
    const __half* __restrict__ fhT, const __half* __restrict__ Vg,
    __half* __restrict__ ctxh)
{
    extern __shared__ __half smh[];
    __half* Qs = smh;                       // [128][264]
    __half* Ks = Qs + 128 * 264;            // [64][264]
    __half* Ps = Ks + 64 * 264;             // [128][72]
    __half* Vs = Ps + 128 * 72;             // [256][72]
    float*  red = (float*)(Vs + 256 * 72);  // [128][4]
    float*  rin = red + 128 * 4;            // [128]

    const int bz = blockIdx.z;
    const __half* F = fhT + (size_t)bz * NN * NCK;
    const __half* V = Vg + (size_t)bz * NCK * NN;
    const int q0 = blockIdx.x * 128;

    const int tid  = threadIdx.x;
    const int warp = tid >> 5;
    const int lane = tid & 31;
    const int wm  = (warp & 1) * 64;
    const int wnS = (warp >> 1) * 16;   // S columns (16 per warp)
    const int wnO = (warp >> 1) * 64;   // O columns (64 per warp)
    const int gid = lane >> 2;
    const int tig = lane & 3;

    // ---- load Q tile (128 x 256) once ----
    {
        const int r = tid >> 1, seg = (tid & 1) * 128;
        const __half* src = F + (size_t)(q0 + r) * NCK + seg;
        __half* dst = Qs + r * 264 + seg;
#pragma unroll
        for (int i = 0; i < 16; i++)
            *(uint4*)(dst + 8 * i) = *(const uint4*)(src + 8 * i);
    }

    float acc_o[4][8][4];
#pragma unroll
    for (int i = 0; i < 4; i++)
#pragma unroll
        for (int j = 0; j < 8; j++)
#pragma unroll
            for (int c = 0; c < 4; c++) acc_o[i][j][c] = 0.f;
    float rsum[4][2];
#pragma unroll
    for (int i = 0; i < 4; i++) { rsum[i][0] = 0.f; rsum[i][1] = 0.f; }

    for (int kt = 0; kt < 64; kt++) {
        const int j0 = kt * 64;
        __syncthreads();   // previous PV reads of Vs/Ps done; Q load done (1st iter)
        // ---- load K tile (64 x 256) ----
        {
            const int r = tid >> 2, seg = (tid & 3) * 64;
            const __half* src = F + (size_t)(j0 + r) * NCK + seg;
            __half* dst = Ks + r * 264 + seg;
#pragma unroll
            for (int i = 0; i < 8; i++)
                *(uint4*)(dst + 8 * i) = *(const uint4*)(src + 8 * i);
        }
        // ---- load V tile (256 cv x 64 j) ----
        {
            const __half* src = V + (size_t)tid * NN + j0;
            __half* dst = Vs + tid * 72;
#pragma unroll
            for (int i = 0; i < 8; i++)
                *(uint4*)(dst + 8 * i) = *(const uint4*)(src + 8 * i);
        }
        __syncthreads();

        // ---- S = Q K^T (128 x 64, k=256) ----
        float s[4][2][4];
#pragma unroll
        for (int i = 0; i < 4; i++)
#pragma unroll
            for (int j = 0; j < 2; j++)
#pragma unroll
                for (int c = 0; c < 4; c++) s[i][j][c] = 0.f;
#pragma unroll
        for (int sl = 0; sl < 16; sl++) {
            const int kk = sl * 16;
            unsigned a[4][4];
#pragma unroll
            for (int mt = 0; mt < 4; mt++) {
                const int mr = wm + mt * 16;
                a[mt][0] = *(const unsigned*)&Qs[(mr + gid) * 264 + kk + 2 * tig];
                a[mt][1] = *(const unsigned*)&Qs[(mr + gid + 8) * 264 + kk + 2 * tig];
                a[mt][2] = *(const unsigned*)&Qs[(mr + gid) * 264 + kk + 2 * tig + 8];
                a[mt][3] = *(const unsigned*)&Qs[(mr + gid + 8) * 264 + kk + 2 * tig + 8];
            }
            unsigned b[2][2];
#pragma unroll
            for (int nt = 0; nt < 2; nt++) {
                const int nr = wnS + nt * 8 + gid;
                b[nt][0] = *(const unsigned*)&Ks[nr * 264 + kk + 2 * tig];
                b[nt][1] = *(const unsigned*)&Ks[nr * 264 + kk + 2 * tig + 8];
            }
#pragma unroll
            for (int mt = 0; mt < 4; mt++)
#pragma unroll
                for (int nt = 0; nt < 2; nt++)
                    mma_f16(s[mt][nt][0], s[mt][nt][1], s[mt][nt][2], s[mt][nt][3],
                            a[mt][0], a[mt][1], a[mt][2], a[mt][3],
                            b[nt][0], b[nt][1]);
        }

        // ---- P = exp(S/16 - SHIFT) -> Ps; accumulate row sums ----
#pragma unroll
        for (int mt = 0; mt < 4; mt++) {
            const int lr = wm + mt * 16 + gid;
#pragma unroll
            for (int nt = 0; nt < 2; nt++) {
                const int lc = wnS + nt * 8 + 2 * tig;
                float e0 = __expf(s[mt][nt][0] * 0.0625f - SM_SHIFT);
                float e1 = __expf(s[mt][nt][1] * 0.0625f - SM_SHIFT);
                float e2 = __expf(s[mt][nt][2] * 0.0625f - SM_SHIFT);
                float e3 = __expf(s[mt][nt][3] * 0.0625f - SM_SHIFT);
                *(__half2*)&Ps[lr * 72 + lc] = __floats2half2_rn(e0, e1);
                *(__half2*)&Ps[(lr + 8) * 72 + lc] = __floats2half2_rn(e2, e3);
                rsum[mt][0] += e0 + e1;
                rsum[mt][1] += e2 + e3;
            }
        }
        __syncthreads();

        // ---- O += P V^T (128 x 256, k=64) ----
#pragma unroll
        for (int sl = 0; sl < 4; sl++) {
            const int kk = sl * 16;
            unsigned a[4][4];
#pragma unroll
            for (int mt = 0; mt < 4; mt++) {
                const int mr = wm + mt * 16;
                a[mt][0] = *(const unsigned*)&Ps[(mr + gid) * 72 + kk + 2 * tig];
                a[mt][1] = *(const unsigned*)&Ps[(mr + gid + 8) * 72 + kk + 2 * tig];
                a[mt][2] = *(const unsigned*)&Ps[(mr + gid) * 72 + kk + 2 * tig + 8];
                a[mt][3] = *(const unsigned*)&Ps[(mr + gid + 8) * 72 + kk + 2 * tig + 8];
            }
            unsigned b[8][2];
#pragma unroll
            for (int nt = 0; nt < 8; nt++) {
                const int nr = wnO + nt * 8 + gid;
                b[nt][0] = *(const unsigned*)&Vs[nr * 72 + kk + 2 * tig];
                b[nt][1] = *(const unsigned*)&Vs[nr * 72 + kk + 2 * tig + 8];
            }
#pragma unroll
            for (int mt = 0; mt < 4; mt++)
#pragma unroll
                for (int nt = 0; nt < 8; nt++)
                    mma_f16(acc_o[mt][nt][0], acc_o[mt][nt][1], acc_o[mt][nt][2], acc_o[mt][nt][3],
                            a[mt][0], a[mt][1], a[mt][2], a[mt][3],
                            b[nt][0], b[nt][1]);
        }
    }

    // ---- rowsum reduce -> rinv ----
#pragma unroll
    for (int mt = 0; mt < 4; mt++)
#pragma unroll
        for (int h = 0; h < 2; h++) {
            float v = rsum[mt][h];
            v += __shfl_xor_sync(0xffffffffu, v, 1);
            v += __shfl_xor_sync(0xffffffffu, v, 2);
            if (tig == 0) red[(wm + mt * 16 + gid + 8 * h) * 4 + (warp >> 1)] = v;
        }
    __syncthreads();
    if (tid < 128)
        rin[tid] = 1.f / (red[tid * 4] + red[tid * 4 + 1] + red[tid * 4 + 2] + red[tid * 4 + 3]);
    __syncthreads();

    // ---- write ctx fp16 [n][cv] ----
    __half* dst = ctxh + (size_t)bz * NN * NCK;
#pragma unroll
    for (int mt = 0; mt < 4; mt++) {
        const int lr = wm + mt * 16 + gid;
        const float w0 = rin[lr];
        const float w1 = rin[lr + 8];
        const int r0 = q0 + lr;
#pragma unroll
        for (int nt = 0; nt < 8; nt++) {
            const int col = wnO + nt * 8 + 2 * tig;
            *(__half2*)&dst[(size_t)r0 * NCK + col] =
                __floats2half2_rn(acc_o[mt][nt][0] * w0, acc_o[mt][nt][1] * w0);
            *(__half2*)&dst[(size_t)(r0 + 8) * NCK + col] =
                __floats2half2_rn(acc_o[mt][nt][2] * w1, acc_o[mt][nt][3] * w1);
        }
    }
}

// ---------------------------------------------------------------------------
__global__ __launch_bounds__(256) void bn_reduce()
{
    const int c = blockIdx.x;
    const int tid = threadIdx.x;
    float s1 = g_bnp1[c * 256 + tid];
    float s2 = g_bnp2[c * 256 + tid];
    __shared__ float sh1[256], sh2[256];
    sh1[tid] = s1; sh2[tid] = s2;
    __syncthreads();
    for (int s = 128; s > 0; s >>= 1) {
        if (tid < s) { sh1[tid] += sh1[tid + s]; sh2[tid] += sh2[tid + s]; }
        __syncthreads();
    }
    if (tid == 0) {
        float m = sh1[0] * (1.f / 32768.f);
        float var = sh2[0] * (1.f / 32768.f) - m * m;
        g_mean[c] = m;
        g_rstd[c] = rsqrtf(var + 1e-5f);
    }
}

// ---------------------------------------------------------------------------
// BN apply + ReLU + transpose: g_qk [c][n] -> feat1/feat2 fp32 + g_fhT fp16 [n][c]
// ---------------------------------------------------------------------------
__global__ __launch_bounds__(256) void bn_fuse(
    const float* __restrict__ gamma, const float* __restrict__ beta,
    float* __restrict__ f1, float* __restrict__ f2)
{
    __shared__ float T[64][65];

    const int bz = blockIdx.z;
    const int n0 = blockIdx.x * 64;
    const int c0 = blockIdx.y * 64;
    const int tid = threadIdx.x;

    const int cr = tid >> 4;
    const int nc4 = (tid & 15) * 4;

#pragma unroll
    for (int i = 0; i < 4; i++) {
        const int c = c0 + cr + 16 * i;
        const size_t base = ((size_t)bz * NCK + c) * NN + n0 + nc4;
        float4 v = *(const float4*)&g_qk[base];
        const float mu = g_mean[c], rs = g_rstd[c], ga = gamma[c], be = beta[c];
        float4 w;
        w.x = fmaxf((v.x - mu) * rs * ga + be, 0.f);
        w.y = fmaxf((v.y - mu) * rs * ga + be, 0.f);
        w.z = fmaxf((v.z - mu) * rs * ga + be, 0.f);
        w.w = fmaxf((v.w - mu) * rs * ga + be, 0.f);
        *(float4*)&f1[base] = w;
        *(float4*)&f2[base] = w;
        T[cr + 16 * i][nc4 + 0] = w.x;
        T[cr + 16 * i][nc4 + 1] = w.y;
        T[cr + 16 * i][nc4 + 2] = w.z;
        T[cr + 16 * i][nc4 + 3] = w.w;
    }
    __syncthreads();

    const int r2 = tid >> 2;
    const int cseg = (tid & 3) * 16;
    __half2 h[8];
#pragma unroll
    for (int u = 0; u < 8; u++)
        h[u] = __floats2half2_rn(T[cseg + 2 * u][r2], T[cseg + 2 * u + 1][r2]);
    uint4 p0 = make_uint4(*(unsigned*)&h[0], *(unsigned*)&h[1],
                          *(unsigned*)&h[2], *(unsigned*)&h[3]);
    uint4 p1 = make_uint4(*(unsigned*)&h[4], *(unsigned*)&h[5],
                          *(unsigned*)&h[6], *(unsigned*)&h[7]);
    __half* dst = g_fhT + ((size_t)bz * NN + n0 + r2) * NCK + c0 + cseg;
    *(uint4*)(dst)     = p0;
    *(uint4*)(dst + 8) = p1;
}

// ---------------------------------------------------------------------------
extern "C" void kernel_launch(void* const* d_in, const int* in_sizes, int n_in,
                              void* d_out, int out_size)
{
    const float* x     = (const float*)d_in[0];
    const float* Wk    = (const float*)d_in[1];
    const float* bk    = (const float*)d_in[2];
    const float* gamma = (const float*)d_in[3];
    const float* beta  = (const float*)d_in[4];
    const float* Wv    = (const float*)d_in[5];
    const float* bv    = (const float*)d_in[6];
    const float* Ww    = (const float*)d_in[7];
    const float* bw    = (const float*)d_in[8];

    float* out   = (float*)d_out;                                    // [8,512,64,64]
    float* feat1 = out + (size_t)NB * NCO * NN;                      // [8,256,64,64]
    float* feat2 = feat1 + (size_t)NB * NCK * NN;                    // [8,256,64,64]
    float* value = feat2 + (size_t)NB * NCK * NN;                    // [8,256,64,64]

    float *qkP;
    __half *vhP, *fhTP, *ctxhP;
    cudaGetSymbolAddress((void**)&qkP,   g_qk);
    cudaGetSymbolAddress((void**)&vhP,   g_vh);
    cudaGetSymbolAddress((void**)&fhTP,  g_fhT);
    cudaGetSymbolAddress((void**)&ctxhP, g_ctxh);

    // flash_attn dynamic SMEM: (128*264 + 64*264 + 128*72 + 256*72)*2 + 128*4*4 + 128*4
    const int FLASH_SMEM = 159232;
    cudaFuncSetAttribute(flash_attn, cudaFuncAttributeMaxDynamicSharedMemorySize, FLASH_SMEM);

    dim3 blk(256);

    // 1) qk[b] = Wk @ x[b] + bk, fused BN partial stats
    gemm_f16<4, false><<<dim3(32, 2, 8), blk>>>(Wk, x, qkP, bk, 512,
        512, 1, 4096, 1, 4096,
        0, (long)NC * NN, (long)NCK * NN, 1.f, nullptr);

    // 2) value[b] = Wv @ x[b] + bv, plus fp16 copy for attention PV
    gemm_f16<3, false><<<dim3(32, 2, 8), blk>>>(Wv, x, value, bv, 512,
        512, 1, 4096, 1, 4096,
        0, (long)NC * NN, (long)NCK * NN, 1.f, vhP);

    // 3) BN stats from partials
    bn_reduce<<<256, blk>>>();

    // 4) feat = relu(BN(qk)) -> feat1, feat2 (fp32) + g_fhT (fp16 transposed)
    bn_fuse<<<dim3(64, 4, 8), blk>>>(gamma, beta, feat1, feat2);

    // 5-7) fused attention: ctx = softmax(F F^T / 16) V -> fp16
    flash_attn<<<dim3(32, 1, 8), blk, FLASH_SMEM>>>(fhTP, vhP, ctxhP);

    // 8) out = Ww @ ctx^T + bw  (B operand fp16)
    gemm_f16<0, true><<<dim3(32, 4, 8), blk>>>(Ww, ctxhP, out, bw, 256,
        256, 1, 1, 256, 4096,
        0, (long)NN * NCK, (long)NCO * NN, 1.f, nullptr);
}

// round 16
// speedup vs baseline: 1.1183x; 1.1183x over previous
#include <cuda_runtime.h>
#include <cuda_fp16.h>
#include <math.h>

// Shapes (fixed per reference): B=8, C=512, Ck=Cv=256, Co=512, H=W=64, N=4096
#define NB 8
#define NC 512
#define NCK 256
#define NCO 512
#define NN 4096

// Softmax shift: logits = (feat_i . feat_j)/16 in [0, ~13.5]; exp(l-8) fp16-safe.
#define SM_SHIFT 8.0f

// Scratch (allocation-free: __device__ globals)
__device__ float  g_qk[(size_t)NB * NCK * NN];          // 33.5 MB: pre-BN qk
__device__ __half g_vh[(size_t)NB * NCK * NN];          // 16.8 MB: value fp16 [cv][n]
__device__ __half g_fhT[(size_t)NB * NN * NCK];         // 16.8 MB: feat fp16 [n][k]
__device__ __half g_ctxh[(size_t)NB * NN * NCK];        // 16.8 MB: ctx fp16 [n][cv]
__device__ float  g_bnp1[NCK * 256];                    // BN partial sums
__device__ float  g_bnp2[NCK * 256];                    // BN partial sq-sums
__device__ float  g_mean[NCK];
__device__ float  g_rstd[NCK];

__device__ __forceinline__ void mma_f16(
    float& c0, float& c1, float& c2, float& c3,
    unsigned a0, unsigned a1, unsigned a2, unsigned a3,
    unsigned b0, unsigned b1)
{
    asm volatile(
        "mma.sync.aligned.m16n8k16.row.col.f32.f16.f16.f32 "
        "{%0,%1,%2,%3}, {%4,%5,%6,%7}, {%8,%9}, {%0,%1,%2,%3};"
        : "+f"(c0), "+f"(c1), "+f"(c2), "+f"(c3)
        : "r"(a0), "r"(a1), "r"(a2), "r"(a3), "r"(b0), "r"(b1));
}

__device__ __forceinline__ void cp16(void* smem, const void* g) {
    unsigned saddr = (unsigned)__cvta_generic_to_shared(smem);
    asm volatile("cp.async.cg.shared.global [%0], [%1], 16;" :: "r"(saddr), "l"(g));
}
__device__ __forceinline__ void cp_commit() {
    asm volatile("cp.async.commit_group;");
}
template<int N>
__device__ __forceinline__ void cp_wait() {
    asm volatile("cp.async.wait_group %0;" :: "n"(N));
}

// ---------------------------------------------------------------------------
// Generic strided fp16-input tensor-core GEMM (convs).
// A fp32 (converted at SMEM store). B fp32 if !BH, fp16 if BH.
// MODE 0: plain.  MODE 3: + fp16 copy of C.  MODE 4: + BN partials.
// ---------------------------------------------------------------------------
template<int MODE, bool BH>
__global__ __launch_bounds__(256, 2) void gemm_f16(
    const float* __restrict__ A, const void* __restrict__ Bv,
    float* __restrict__ C, const float* __restrict__ bias,
    int K,
    long sa_m, long sa_k, long sb_k, long sb_n, long sc_m,
    long bA, long bB, long bC, float alpha,
    __half* __restrict__ Ch)
{
    __shared__ __half As[128][40];
    __shared__ __half Bs[128][40];
    __shared__ float red1[128][4];
    __shared__ float red2[128][4];

    const int bz = blockIdx.z;
    A += (size_t)bz * bA;
    const float*  Bf  = (const float*)Bv + (BH ? 0 : (size_t)bz * bB);
    const __half* Bhp = (const __half*)Bv + (BH ? (size_t)bz * bB : 0);
    C += (size_t)bz * bC;
    if (MODE == 3) Ch += (size_t)bz * bC;

    const int m0 = blockIdx.y * 128;
    const int n0 = blockIdx.x * 128;
    const int tid  = threadIdx.x;
    const int warp = tid >> 5;
    const int lane = tid & 31;
    const int wm = (warp & 1) * 64;
    const int wn = (warp >> 1) * 32;
    const int gid = lane >> 2;
    const int tig = lane & 3;

    float acc[4][4][4];
#pragma unroll
    for (int i = 0; i < 4; i++)
#pragma unroll
        for (int j = 0; j < 4; j++)
#pragma unroll
            for (int c = 0; c < 4; c++) acc[i][j][c] = 0.f;

    for (int k0 = 0; k0 < K; k0 += 32) {
        if (sa_k == 1) {
            const int m = tid >> 3, kq = (tid & 7) * 4;
#pragma unroll
            for (int i = 0; i < 4; i++) {
                float4 v = *(const float4*)&A[(size_t)(m0 + m + 32 * i) * sa_m + (size_t)(k0 + kq)];
                __half2 h0 = __floats2half2_rn(v.x, v.y);
                __half2 h1 = __floats2half2_rn(v.z, v.w);
                *(uint2*)&As[m + 32 * i][kq] = make_uint2(*(unsigned*)&h0, *(unsigned*)&h1);
            }
        } else {
            const int m = tid & 127, kb = (tid >> 7) * 16;
            const float* Ap = A + (size_t)(m0 + m) + (size_t)(k0 + kb) * sa_k;
#pragma unroll
            for (int q = 0; q < 4; q++) {
                __half2 h0 = __floats2half2_rn(Ap[(size_t)(q * 4 + 0) * sa_k],
                                               Ap[(size_t)(q * 4 + 1) * sa_k]);
                __half2 h1 = __floats2half2_rn(Ap[(size_t)(q * 4 + 2) * sa_k],
                                               Ap[(size_t)(q * 4 + 3) * sa_k]);
                *(uint2*)&As[m][kb + q * 4] = make_uint2(*(unsigned*)&h0, *(unsigned*)&h1);
            }
        }
        if (sb_n == 1) {
            const int n = tid & 127, kb = (tid >> 7) * 16;
            if (!BH) {
                const float* Bp = Bf + (size_t)(n0 + n) + (size_t)(k0 + kb) * sb_k;
#pragma unroll
                for (int q = 0; q < 4; q++) {
                    __half2 h0 = __floats2half2_rn(Bp[(size_t)(q * 4 + 0) * sb_k],
                                                   Bp[(size_t)(q * 4 + 1) * sb_k]);
                    __half2 h1 = __floats2half2_rn(Bp[(size_t)(q * 4 + 2) * sb_k],
                                                   Bp[(size_t)(q * 4 + 3) * sb_k]);
                    *(uint2*)&Bs[n][kb + q * 4] = make_uint2(*(unsigned*)&h0, *(unsigned*)&h1);
                }
            } else {
                const __half* Bp = Bhp + (size_t)(n0 + n) + (size_t)(k0 + kb) * sb_k;
#pragma unroll
                for (int q = 0; q < 16; q++)
                    Bs[n][kb + q] = Bp[(size_t)q * sb_k];
            }
        } else {  // sb_k == 1
            const int n = tid >> 3, kq = (tid & 7) * 4;
            if (!BH) {
#pragma unroll
                for (int i = 0; i < 4; i++) {
                    float4 v = *(const float4*)&Bf[(size_t)(n0 + n + 32 * i) * sb_n + (size_t)(k0 + kq)];
                    __half2 h0 = __floats2half2_rn(v.x, v.y);
                    __half2 h1 = __floats2half2_rn(v.z, v.w);
                    *(uint2*)&Bs[n + 32 * i][kq] = make_uint2(*(unsigned*)&h0, *(unsigned*)&h1);
                }
            } else {
#pragma unroll
                for (int i = 0; i < 4; i++) {
                    uint2 v = *(const uint2*)&Bhp[(size_t)(n0 + n + 32 * i) * sb_n + (size_t)(k0 + kq)];
                    *(uint2*)&Bs[n + 32 * i][kq] = v;
                }
            }
        }
        __syncthreads();

#pragma unroll
        for (int sl = 0; sl < 2; sl++) {
            const int kk = sl * 16;
            unsigned a[4][4];
#pragma unroll
            for (int mt = 0; mt < 4; mt++) {
                const int mr = wm + mt * 16;
                a[mt][0] = *(const unsigned*)&As[mr + gid][kk + 2 * tig];
                a[mt][1] = *(const unsigned*)&As[mr + gid + 8][kk + 2 * tig];
                a[mt][2] = *(const unsigned*)&As[mr + gid][kk + 2 * tig + 8];
                a[mt][3] = *(const unsigned*)&As[mr + gid + 8][kk + 2 * tig + 8];
            }
            unsigned b[4][2];
#pragma unroll
            for (int nt = 0; nt < 4; nt++) {
                const int nr = wn + nt * 8 + gid;
                b[nt][0] = *(const unsigned*)&Bs[nr][kk + 2 * tig];
                b[nt][1] = *(const unsigned*)&Bs[nr][kk + 2 * tig + 8];
            }
#pragma unroll
            for (int mt = 0; mt < 4; mt++)
#pragma unroll
                for (int nt = 0; nt < 4; nt++)
                    mma_f16(acc[mt][nt][0], acc[mt][nt][1], acc[mt][nt][2], acc[mt][nt][3],
                            a[mt][0], a[mt][1], a[mt][2], a[mt][3],
                            b[nt][0], b[nt][1]);
        }
        __syncthreads();
    }

#pragma unroll
    for (int mt = 0; mt < 4; mt++) {
        const int r0 = m0 + wm + mt * 16 + gid;
        const float bb0 = bias ? bias[r0] : 0.f;
        const float bb1 = bias ? bias[r0 + 8] : 0.f;
        float s1a = 0.f, s2a = 0.f, s1b = 0.f, s2b = 0.f;
#pragma unroll
        for (int nt = 0; nt < 4; nt++) {
            const int col = n0 + wn + nt * 8 + 2 * tig;
            float2 v0 = make_float2(acc[mt][nt][0] * alpha + bb0, acc[mt][nt][1] * alpha + bb0);
            float2 v1 = make_float2(acc[mt][nt][2] * alpha + bb1, acc[mt][nt][3] * alpha + bb1);
            *(float2*)&C[(size_t)r0 * sc_m + col] = v0;
            *(float2*)&C[(size_t)(r0 + 8) * sc_m + col] = v1;
            if (MODE == 3) {
                *(__half2*)&Ch[(size_t)r0 * sc_m + col] = __floats2half2_rn(v0.x, v0.y);
                *(__half2*)&Ch[(size_t)(r0 + 8) * sc_m + col] = __floats2half2_rn(v1.x, v1.y);
            }
            if (MODE == 4) {
                s1a += v0.x + v0.y;
                s2a = fmaf(v0.x, v0.x, fmaf(v0.y, v0.y, s2a));
                s1b += v1.x + v1.y;
                s2b = fmaf(v1.x, v1.x, fmaf(v1.y, v1.y, s2b));
            }
        }
        if (MODE == 4) {
            s1a += __shfl_xor_sync(0xffffffffu, s1a, 1);
            s1a += __shfl_xor_sync(0xffffffffu, s1a, 2);
            s2a += __shfl_xor_sync(0xffffffffu, s2a, 1);
            s2a += __shfl_xor_sync(0xffffffffu, s2a, 2);
            s1b += __shfl_xor_sync(0xffffffffu, s1b, 1);
            s1b += __shfl_xor_sync(0xffffffffu, s1b, 2);
            s2b += __shfl_xor_sync(0xffffffffu, s2b, 1);
            s2b += __shfl_xor_sync(0xffffffffu, s2b, 2);
            if (tig == 0) {
                const int lr = wm + mt * 16 + gid;
                const int nw = warp >> 1;
                red1[lr][nw] = s1a;  red2[lr][nw] = s2a;
                red1[lr + 8][nw] = s1b;  red2[lr + 8][nw] = s2b;
            }
        }
    }
    if (MODE == 4) {
        __syncthreads();
        if (tid < 128) {
            float S1 = red1[tid][0] + red1[tid][1] + red1[tid][2] + red1[tid][3];
            float S2 = red2[tid][0] + red2[tid][1] + red2[tid][2] + red2[tid][3];
            const int slot = bz * 32 + blockIdx.x;
            g_bnp1[(m0 + tid) * 256 + slot] = S1;
            g_bnp2[(m0 + tid) * 256 + slot] = S2;
        }
    }
}

// ---------------------------------------------------------------------------
// Fused flash attention, cp.async pipelined:
//  Q tile 128x256 resident; loop 64-key tiles: prefetch V[kt] + K[kt+1]
//  (K double-buffered) under S = Q K^T; P = exp(S/16-8) -> SMEM; O += P V^T.
//  Epilogue: ctx = O / rowsum (fp32 sums) -> fp16 [n][cv].
// ---------------------------------------------------------------------------
__global__ __launch_bounds__(256, 1) void flash_attn(
    const __half* __restrict__ fhT, const __half* __restrict__ Vg,
    __half* __restrict__ ctxh)
{
    extern __shared__ __half smh[];
    __half* Qs  = smh;                      // [128][264]  67584 B
    __half* Ks0 = Qs + 128 * 264;           // [64][264]   33792 B
    __half* Ks1 = Ks0 + 64 * 264;           // [64][264]   33792 B
    __half* Vs  = Ks1 + 64 * 264;           // [256][72]   36864 B
    __half* Ps  = Vs + 256 * 72;            // [128][72]   18432 B
    float*  red = (float*)Qs;               // overlay (Qs dead after loop)
    float*  rin = red + 128 * 4;

    const int bz = blockIdx.z;
    const __half* F = fhT + (size_t)bz * NN * NCK;
    const __half* V = Vg + (size_t)bz * NCK * NN;
    const int q0 = blockIdx.x * 128;

    const int tid  = threadIdx.x;
    const int warp = tid >> 5;
    const int lane = tid & 31;
    const int wm  = (warp & 1) * 64;
    const int wnS = (warp >> 1) * 16;
    const int wnO = (warp >> 1) * 64;
    const int gid = lane >> 2;
    const int tig = lane & 3;

    // ---- preload K0 via cp.async (group 0) ----
    const int kr = tid >> 2, kseg = (tid & 3) * 64;
    {
        const __half* src = F + (size_t)kr * NCK + kseg;
        __half* dst = Ks0 + kr * 264 + kseg;
#pragma unroll
        for (int i = 0; i < 8; i++) cp16(dst + 8 * i, src + 8 * i);
    }
    cp_commit();

    // ---- load Q tile (128 x 256) once (regular loads) ----
    {
        const int r = tid >> 1, seg = (tid & 1) * 128;
        const __half* src = F + (size_t)(q0 + r) * NCK + seg;
        __half* dst = Qs + r * 264 + seg;
#pragma unroll
        for (int i = 0; i < 16; i++)
            *(uint4*)(dst + 8 * i) = *(const uint4*)(src + 8 * i);
    }

    float acc_o[4][8][4];
#pragma unroll
    for (int i = 0; i < 4; i++)
#pragma unroll
        for (int j = 0; j < 8; j++)
#pragma unroll
            for (int c = 0; c < 4; c++) acc_o[i][j][c] = 0.f;
    float rsum[4][2];
#pragma unroll
    for (int i = 0; i < 4; i++) { rsum[i][0] = 0.f; rsum[i][1] = 0.f; }

    for (int kt = 0; kt < 64; kt++) {
        const int j0 = kt * 64;
        __half* Kcur = (kt & 1) ? Ks1 : Ks0;
        __half* Knxt = (kt & 1) ? Ks0 : Ks1;

        __syncthreads();   // prior PV done: Vs/Ps/Knxt free for refill

        // ---- issue async: V[kt] and K[kt+1] ----
        {
            const __half* src = V + (size_t)tid * NN + j0;
            __half* dst = Vs + tid * 72;
#pragma unroll
            for (int i = 0; i < 8; i++) cp16(dst + 8 * i, src + 8 * i);
        }
        if (kt < 63) {
            const __half* src = F + (size_t)(j0 + 64 + kr) * NCK + kseg;
            __half* dst = Knxt + kr * 264 + kseg;
#pragma unroll
            for (int i = 0; i < 8; i++) cp16(dst + 8 * i, src + 8 * i);
        }
        cp_commit();

        cp_wait<1>();      // K[kt] landed (V[kt]/K[kt+1] may be in flight)
        __syncthreads();

        // ---- S = Q Kcur^T (128 x 64, k=256), overlapped with V/K prefetch ----
        float s[4][2][4];
#pragma unroll
        for (int i = 0; i < 4; i++)
#pragma unroll
            for (int j = 0; j < 2; j++)
#pragma unroll
                for (int c = 0; c < 4; c++) s[i][j][c] = 0.f;
#pragma unroll
        for (int sl = 0; sl < 16; sl++) {
            const int kk = sl * 16;
            unsigned a[4][4];
#pragma unroll
            for (int mt = 0; mt < 4; mt++) {
                const int mr = wm + mt * 16;
                a[mt][0] = *(const unsigned*)&Qs[(mr + gid) * 264 + kk + 2 * tig];
                a[mt][1] = *(const unsigned*)&Qs[(mr + gid + 8) * 264 + kk + 2 * tig];
                a[mt][2] = *(const unsigned*)&Qs[(mr + gid) * 264 + kk + 2 * tig + 8];
                a[mt][3] = *(const unsigned*)&Qs[(mr + gid + 8) * 264 + kk + 2 * tig + 8];
            }
            unsigned b[2][2];
#pragma unroll
            for (int nt = 0; nt < 2; nt++) {
                const int nr = wnS + nt * 8 + gid;
                b[nt][0] = *(const unsigned*)&Kcur[nr * 264 + kk + 2 * tig];
                b[nt][1] = *(const unsigned*)&Kcur[nr * 264 + kk + 2 * tig + 8];
            }
#pragma unroll
            for (int mt = 0; mt < 4; mt++)
#pragma unroll
                for (int nt = 0; nt < 2; nt++)
                    mma_f16(s[mt][nt][0], s[mt][nt][1], s[mt][nt][2], s[mt][nt][3],
                            a[mt][0], a[mt][1], a[mt][2], a[mt][3],
                            b[nt][0], b[nt][1]);
        }

        // ---- P = exp(S/16 - SHIFT) -> Ps; accumulate row sums ----
#pragma unroll
        for (int mt = 0; mt < 4; mt++) {
            const int lr = wm + mt * 16 + gid;
#pragma unroll
            for (int nt = 0; nt < 2; nt++) {
                const int lc = wnS + nt * 8 + 2 * tig;
                float e0 = __expf(fmaf(s[mt][nt][0], 0.0625f, -SM_SHIFT));
                float e1 = __expf(fmaf(s[mt][nt][1], 0.0625f, -SM_SHIFT));
                float e2 = __expf(fmaf(s[mt][nt][2], 0.0625f, -SM_SHIFT));
                float e3 = __expf(fmaf(s[mt][nt][3], 0.0625f, -SM_SHIFT));
                *(__half2*)&Ps[lr * 72 + lc] = __floats2half2_rn(e0, e1);
                *(__half2*)&Ps[(lr + 8) * 72 + lc] = __floats2half2_rn(e2, e3);
                rsum[mt][0] += e0 + e1;
                rsum[mt][1] += e2 + e3;
            }
        }

        cp_wait<0>();      // V[kt] landed
        __syncthreads();   // Ps + Vs visible to all

        // ---- O += P V^T (128 x 256, k=64) ----
#pragma unroll
        for (int sl = 0; sl < 4; sl++) {
            const int kk = sl * 16;
            unsigned a[4][4];
#pragma unroll
            for (int mt = 0; mt < 4; mt++) {
                const int mr = wm + mt * 16;
                a[mt][0] = *(const unsigned*)&Ps[(mr + gid) * 72 + kk + 2 * tig];
                a[mt][1] = *(const unsigned*)&Ps[(mr + gid + 8) * 72 + kk + 2 * tig];
                a[mt][2] = *(const unsigned*)&Ps[(mr + gid) * 72 + kk + 2 * tig + 8];
                a[mt][3] = *(const unsigned*)&Ps[(mr + gid + 8) * 72 + kk + 2 * tig + 8];
            }
            unsigned b[8][2];
#pragma unroll
            for (int nt = 0; nt < 8; nt++) {
                const int nr = wnO + nt * 8 + gid;
                b[nt][0] = *(const unsigned*)&Vs[nr * 72 + kk + 2 * tig];
                b[nt][1] = *(const unsigned*)&Vs[nr * 72 + kk + 2 * tig + 8];
            }
#pragma unroll
            for (int mt = 0; mt < 4; mt++)
#pragma unroll
                for (int nt = 0; nt < 8; nt++)
                    mma_f16(acc_o[mt][nt][0], acc_o[mt][nt][1], acc_o[mt][nt][2], acc_o[mt][nt][3],
                            a[mt][0], a[mt][1], a[mt][2], a[mt][3],
                            b[nt][0], b[nt][1]);
        }
    }

    // ---- rowsum reduce -> rinv (red/rin overlay Qs; Qs dead) ----
    __syncthreads();
#pragma unroll
    for (int mt = 0; mt < 4; mt++)
#pragma unroll
        for (int h = 0; h < 2; h++) {
            float v = rsum[mt][h];
            v += __shfl_xor_sync(0xffffffffu, v, 1);
            v += __shfl_xor_sync(0xffffffffu, v, 2);
            if (tig == 0) red[(wm + mt * 16 + gid + 8 * h) * 4 + (warp >> 1)] = v;
        }
    __syncthreads();
    if (tid < 128)
        rin[tid] = 1.f / (red[tid * 4] + red[tid * 4 + 1] + red[tid * 4 + 2] + red[tid * 4 + 3]);
    __syncthreads();

    // ---- write ctx fp16 [n][cv] ----
    __half* dst = ctxh + (size_t)bz * NN * NCK;
#pragma unroll
    for (int mt = 0; mt < 4; mt++) {
        const int lr = wm + mt * 16 + gid;
        const float w0 = rin[lr];
        const float w1 = rin[lr + 8];
        const int r0 = q0 + lr;
#pragma unroll
        for (int nt = 0; nt < 8; nt++) {
            const int col = wnO + nt * 8 + 2 * tig;
            *(__half2*)&dst[(size_t)r0 * NCK + col] =
                __floats2half2_rn(acc_o[mt][nt][0] * w0, acc_o[mt][nt][1] * w0);
            *(__half2*)&dst[(size_t)(r0 + 8) * NCK + col] =
                __floats2half2_rn(acc_o[mt][nt][2] * w1, acc_o[mt][nt][3] * w1);
        }
    }
}

// ---------------------------------------------------------------------------
__global__ __launch_bounds__(256) void bn_reduce()
{
    const int c = blockIdx.x;
    const int tid = threadIdx.x;
    float s1 = g_bnp1[c * 256 + tid];
    float s2 = g_bnp2[c * 256 + tid];
    __shared__ float sh1[256], sh2[256];
    sh1[tid] = s1; sh2[tid] = s2;
    __syncthreads();
    for (int s = 128; s > 0; s >>= 1) {
        if (tid < s) { sh1[tid] += sh1[tid + s]; sh2[tid] += sh2[tid + s]; }
        __syncthreads();
    }
    if (tid == 0) {
        float m = sh1[0] * (1.f / 32768.f);
        float var = sh2[0] * (1.f / 32768.f) - m * m;
        g_mean[c] = m;
        g_rstd[c] = rsqrtf(var + 1e-5f);
    }
}

// ---------------------------------------------------------------------------
// BN apply + ReLU + transpose: g_qk [c][n] -> feat1/feat2 fp32 + g_fhT fp16 [n][c]
// ---------------------------------------------------------------------------
__global__ __launch_bounds__(256) void bn_fuse(
    const float* __restrict__ gamma, const float* __restrict__ beta,
    float* __restrict__ f1, float* __restrict__ f2)
{
    __shared__ float T[64][65];

    const int bz = blockIdx.z;
    const int n0 = blockIdx.x * 64;
    const int c0 = blockIdx.y * 64;
    const int tid = threadIdx.x;

    const int cr = tid >> 4;
    const int nc4 = (tid & 15) * 4;

#pragma unroll
    for (int i = 0; i < 4; i++) {
        const int c = c0 + cr + 16 * i;
        const size_t base = ((size_t)bz * NCK + c) * NN + n0 + nc4;
        float4 v = *(const float4*)&g_qk[base];
        const float mu = g_mean[c], rs = g_rstd[c], ga = gamma[c], be = beta[c];
        float4 w;
        w.x = fmaxf((v.x - mu) * rs * ga + be, 0.f);
        w.y = fmaxf((v.y - mu) * rs * ga + be, 0.f);
        w.z = fmaxf((v.z - mu) * rs * ga + be, 0.f);
        w.w = fmaxf((v.w - mu) * rs * ga + be, 0.f);
        *(float4*)&f1[base] = w;
        *(float4*)&f2[base] = w;
        T[cr + 16 * i][nc4 + 0] = w.x;
        T[cr + 16 * i][nc4 + 1] = w.y;
        T[cr + 16 * i][nc4 + 2] = w.z;
        T[cr + 16 * i][nc4 + 3] = w.w;
    }
    __syncthreads();

    const int r2 = tid >> 2;
    const int cseg = (tid & 3) * 16;
    __half2 h[8];
#pragma unroll
    for (int u = 0; u < 8; u++)
        h[u] = __floats2half2_rn(T[cseg + 2 * u][r2], T[cseg + 2 * u + 1][r2]);
    uint4 p0 = make_uint4(*(unsigned*)&h[0], *(unsigned*)&h[1],
                          *(unsigned*)&h[2], *(unsigned*)&h[3]);
    uint4 p1 = make_uint4(*(unsigned*)&h[4], *(unsigned*)&h[5],
                          *(unsigned*)&h[6], *(unsigned*)&h[7]);
    __half* dst = g_fhT + ((size_t)bz * NN + n0 + r2) * NCK + c0 + cseg;
    *(uint4*)(dst)     = p0;
    *(uint4*)(dst + 8) = p1;
}

// ---------------------------------------------------------------------------
extern "C" void kernel_launch(void* const* d_in, const int* in_sizes, int n_in,
                              void* d_out, int out_size)
{
    const float* x     = (const float*)d_in[0];
    const float* Wk    = (const float*)d_in[1];
    const float* bk    = (const float*)d_in[2];
    const float* gamma = (const float*)d_in[3];
    const float* beta  = (const float*)d_in[4];
    const float* Wv    = (const float*)d_in[5];
    const float* bv    = (const float*)d_in[6];
    const float* Ww    = (const float*)d_in[7];
    const float* bw    = (const float*)d_in[8];

    float* out   = (float*)d_out;                                    // [8,512,64,64]
    float* feat1 = out + (size_t)NB * NCO * NN;                      // [8,256,64,64]
    float* feat2 = feat1 + (size_t)NB * NCK * NN;                    // [8,256,64,64]
    float* value = feat2 + (size_t)NB * NCK * NN;                    // [8,256,64,64]

    float *qkP;
    __half *vhP, *fhTP, *ctxhP;
    cudaGetSymbolAddress((void**)&qkP,   g_qk);
    cudaGetSymbolAddress((void**)&vhP,   g_vh);
    cudaGetSymbolAddress((void**)&fhTP,  g_fhT);
    cudaGetSymbolAddress((void**)&ctxhP, g_ctxh);

    // flash_attn dynamic SMEM: (128*264 + 2*64*264 + 256*72 + 128*72) * 2 B
    const int FLASH_SMEM = 190464;
    cudaFuncSetAttribute(flash_attn, cudaFuncAttributeMaxDynamicSharedMemorySize, FLASH_SMEM);

    dim3 blk(256);

    // 1) qk[b] = Wk @ x[b] + bk, fused BN partial stats
    gemm_f16<4, false><<<dim3(32, 2, 8), blk>>>(Wk, x, qkP, bk, 512,
        512, 1, 4096, 1, 4096,
        0, (long)NC * NN, (long)NCK * NN, 1.f, nullptr);

    // 2) value[b] = Wv @ x[b] + bv, plus fp16 copy for attention PV
    gemm_f16<3, false><<<dim3(32, 2, 8), blk>>>(Wv, x, value, bv, 512,
        512, 1, 4096, 1, 4096,
        0, (long)NC * NN, (long)NCK * NN, 1.f, vhP);

    // 3) BN stats from partials
    bn_reduce<<<256, blk>>>();

    // 4) feat = relu(BN(qk)) -> feat1, feat2 (fp32) + g_fhT (fp16 transposed)
    bn_fuse<<<dim3(64, 4, 8), blk>>>(gamma, beta, feat1, feat2);

    // 5-7) fused attention: ctx = softmax(F F^T / 16) V -> fp16
    flash_attn<<<dim3(32, 1, 8), blk, FLASH_SMEM>>>(fhTP, vhP, ctxhP);

    // 8) out = Ww @ ctx^T + bw  (B operand fp16)
    gemm_f16<0, true><<<dim3(32, 4, 8), blk>>>(Ww, ctxhP, out, bw, 256,
        256, 1, 1, 256, 4096,
        0, (long)NN * NCK, (long)NCO * NN, 1.f, nullptr);
}